// round 1
// baseline (speedup 1.0000x reference)
#include <cuda_runtime.h>
#include <math.h>

// ---------------------------------------------------------------------------
// RotatedIoULoss: per-box rotated-rect IoU -> -log(max(iou,eps))*weight -> mean
//
// Matches the JAX reference numerically (f32 throughout, double final acc):
//  - corners from (x,y,w,h,a) with tx=[.5,-.5,-.5,.5], ty=[.5,.5,-.5,-.5]
//  - 16 edge-pair intersection candidates with (0,1)-open t,u tests
//  - 4+4 corner-containment candidates
//  - valid verts compacted, sorted by atan2 around masked centroid
//  - shoelace in ABSOLUTE coords (identical to reference's first-replication)
//  - area only if num>=3; iou = inter/(a1+a2-inter); loss = -log(max(iou,eps))*w
// ---------------------------------------------------------------------------

#define IOU_EPS 1e-6f

__device__ double g_acc;

__global__ void rl_zero_kernel() { g_acc = 0.0; }

__global__ void rl_final_kernel(float* out, float inv_n) {
    out[0] = (float)(g_acc * (double)inv_n);
}

__device__ __forceinline__ float crossf(float ax, float ay, float bx, float by) {
    return ax * by - ay * bx;
}

__global__ void __launch_bounds__(256)
rl_main_kernel(const float* __restrict__ pred,
               const float* __restrict__ target,
               const float* __restrict__ weight,
               int n) {
    int i = blockIdx.x * blockDim.x + threadIdx.x;
    float loss = 0.0f;

    if (i < n) {
        // ---- load boxes ----
        float p0 = pred[i * 5 + 0], p1 = pred[i * 5 + 1];
        float pw = pred[i * 5 + 2], ph = pred[i * 5 + 3], pa = pred[i * 5 + 4];
        float q0 = target[i * 5 + 0], q1 = target[i * 5 + 1];
        float qw = target[i * 5 + 2], qh = target[i * 5 + 3], qa = target[i * 5 + 4];

        // ---- corners ----
        const float tx[4] = {0.5f, -0.5f, -0.5f, 0.5f};
        const float ty[4] = {0.5f, 0.5f, -0.5f, -0.5f};
        float c1x[4], c1y[4], c2x[4], c2y[4];
        {
            float ca, sa;
            __sincosf(pa, &sa, &ca);      // fast path; refine below if needed
            ca = cosf(pa); sa = sinf(pa); // use accurate versions to match ref
#pragma unroll
            for (int k = 0; k < 4; k++) {
                float cx = tx[k] * pw, cy = ty[k] * ph;
                c1x[k] = cx * ca - cy * sa + p0;
                c1y[k] = cx * sa + cy * ca + p1;
            }
            ca = cosf(qa); sa = sinf(qa);
#pragma unroll
            for (int k = 0; k < 4; k++) {
                float cx = tx[k] * qw, cy = ty[k] * qh;
                c2x[k] = cx * ca - cy * sa + q0;
                c2y[k] = cx * sa + cy * ca + q1;
            }
        }

        // ---- collect valid vertices (compacted) ----
        float vx[24], vy[24];
        int m = 0;
        float sx = 0.0f, sy = 0.0f;

        // corners of box1 inside box2
        {
            float ax = c2x[0], ay = c2y[0];
            float abx = c2x[1] - ax, aby = c2y[1] - ay;
            float adx = c2x[3] - ax, ady = c2y[3] - ay;
            float nab = abx * abx + aby * aby;
            float nad = adx * adx + ady * ady;
#pragma unroll
            for (int k = 0; k < 4; k++) {
                float amx = c1x[k] - ax, amy = c1y[k] - ay;
                float pab = amx * abx + amy * aby;
                float pad = amx * adx + amy * ady;
                if (pab > 0.0f && pab < nab && pad > 0.0f && pad < nad) {
                    vx[m] = c1x[k]; vy[m] = c1y[k];
                    sx += c1x[k]; sy += c1y[k];
                    m++;
                }
            }
        }
        // corners of box2 inside box1
        {
            float ax = c1x[0], ay = c1y[0];
            float abx = c1x[1] - ax, aby = c1y[1] - ay;
            float adx = c1x[3] - ax, ady = c1y[3] - ay;
            float nab = abx * abx + aby * aby;
            float nad = adx * adx + ady * ady;
#pragma unroll
            for (int k = 0; k < 4; k++) {
                float amx = c2x[k] - ax, amy = c2y[k] - ay;
                float pab = amx * abx + amy * aby;
                float pad = amx * adx + amy * ady;
                if (pab > 0.0f && pab < nab && pad > 0.0f && pad < nad) {
                    vx[m] = c2x[k]; vy[m] = c2y[k];
                    sx += c2x[k]; sy += c2y[k];
                    m++;
                }
            }
        }
        // edge x edge intersections
#pragma unroll
        for (int a = 0; a < 4; a++) {
            int a1i = (a + 1) & 3;
            float p1x = c1x[a], p1y = c1y[a];
            float d1x = c1x[a1i] - p1x, d1y = c1y[a1i] - p1y;
#pragma unroll
            for (int b = 0; b < 4; b++) {
                int b1i = (b + 1) & 3;
                float p2x = c2x[b], p2y = c2y[b];
                float d2x = c2x[b1i] - p2x, d2y = c2y[b1i] - p2y;
                float den = crossf(d1x, d1y, d2x, d2y);
                if (den != 0.0f) {
                    float dpx = p2x - p1x, dpy = p2y - p1y;
                    float t = crossf(dpx, dpy, d2x, d2y) / den;
                    float u = crossf(dpx, dpy, d1x, d1y) / den;
                    if (t > 0.0f && t < 1.0f && u > 0.0f && u < 1.0f) {
                        float ix = p1x + t * d1x;
                        float iy = p1y + t * d1y;
                        vx[m] = ix; vy[m] = iy;
                        sx += ix; sy += iy;
                        m++;
                    }
                }
            }
        }

        // ---- polygon area via angular sort + shoelace ----
        float inter = 0.0f;
        if (m >= 3) {
            float inv_m = 1.0f / (float)m;
            float cx0 = sx * inv_m, cy0 = sy * inv_m;
            float ang[24];
            for (int k = 0; k < m; k++) {
                ang[k] = atan2f(vy[k] - cy0, vx[k] - cx0);
            }
            // stable insertion sort by angle (small m: typically 3..8)
            for (int k = 1; k < m; k++) {
                float ka = ang[k], kx = vx[k], ky = vy[k];
                int j = k - 1;
                while (j >= 0 && ang[j] > ka) {
                    ang[j + 1] = ang[j];
                    vx[j + 1] = vx[j];
                    vy[j + 1] = vy[j];
                    j--;
                }
                ang[j + 1] = ka; vx[j + 1] = kx; vy[j + 1] = ky;
            }
            // shoelace (absolute coordinates, same as reference)
            float s = 0.0f;
            for (int k = 0; k < m; k++) {
                int kn = (k + 1 == m) ? 0 : k + 1;
                s += vx[k] * vy[kn] - vy[k] * vx[kn];
            }
            inter = 0.5f * fabsf(s);
        }

        float a1 = pw * ph;
        float a2 = qw * qh;
        float iou = inter / (a1 + a2 - inter);
        iou = fmaxf(iou, IOU_EPS);
        loss = -logf(iou) * weight[i];
    }

    // ---- block reduction ----
    unsigned mask = 0xFFFFFFFFu;
#pragma unroll
    for (int o = 16; o > 0; o >>= 1)
        loss += __shfl_down_sync(mask, loss, o);

    __shared__ float ws[8];
    int lane = threadIdx.x & 31;
    int wid = threadIdx.x >> 5;
    if (lane == 0) ws[wid] = loss;
    __syncthreads();
    if (wid == 0) {
        float v = (lane < (int)(blockDim.x >> 5)) ? ws[lane] : 0.0f;
#pragma unroll
        for (int o = 4; o > 0; o >>= 1)
            v += __shfl_down_sync(mask, v, o);
        if (lane == 0) atomicAdd(&g_acc, (double)v);
    }
}

extern "C" void kernel_launch(void* const* d_in, const int* in_sizes, int n_in,
                              void* d_out, int out_size) {
    const float* pred   = (const float*)d_in[0];
    const float* target = (const float*)d_in[1];
    const float* weight = (const float*)d_in[2];
    float* out = (float*)d_out;
    int n = in_sizes[2];  // weight element count == number of boxes

    rl_zero_kernel<<<1, 1>>>();
    int block = 256;
    int grid = (n + block - 1) / block;
    rl_main_kernel<<<grid, block>>>(pred, target, weight, n);
    rl_final_kernel<<<1, 1>>>(out, 1.0f / (float)n);
}

// round 2
// speedup vs baseline: 1.2901x; 1.2901x over previous
#include <cuda_runtime.h>
#include <math.h>

// ---------------------------------------------------------------------------
// RotatedIoULoss via Sutherland-Hodgman convex clipping.
//
// The reference builds the intersection polygon of two rotated rectangles by
// collecting contained corners + 16 edge-pair intersections, then sorting by
// angle and applying the shoelace formula. The intersection of two convex
// quads IS a convex polygon (<=8 verts); clipping quad1 by quad2's four
// half-planes produces the identical polygon already in cyclic order:
// no atan2, no sort, far fewer divides. Area differences vs the reference are
// fp-rounding / measure-zero boundary cases only.
//
// loss = mean( -log(max(inter/(a1+a2-inter), 1e-6)) * weight )
// ---------------------------------------------------------------------------

#define IOU_EPS 1e-6f
#define BLOCK 256
#define MAXB  8192

__device__ float g_partial[MAXB];

__device__ __forceinline__ float xcross(float ax, float ay, float bx, float by) {
    return ax * by - ay * bx;
}

__global__ void __launch_bounds__(BLOCK)
rl_main(const float* __restrict__ pred,
        const float* __restrict__ target,
        const float* __restrict__ weight,
        int n) {
    // ---- coalesced staging of stride-5 rows ----
    __shared__ float sp[BLOCK * 5];
    __shared__ float st[BLOCK * 5];
    int bbase = blockIdx.x * BLOCK;
    int gbase = bbase * 5;
    int limit = n * 5 - gbase;
    for (int j = threadIdx.x; j < BLOCK * 5; j += BLOCK) {
        float vp = 0.f, vt = 0.f;
        if (j < limit) { vp = pred[gbase + j]; vt = target[gbase + j]; }
        sp[j] = vp; st[j] = vt;
    }
    __syncthreads();

    int i = bbase + threadIdx.x;
    float loss = 0.f;
    if (i < n) {
        const float* P = sp + threadIdx.x * 5;
        const float* T = st + threadIdx.x * 5;
        float px = P[0], py = P[1], pw = P[2], ph = P[3], pa = P[4];
        float qx = T[0], qy = T[1], qw = T[2], qh = T[3], qa = T[4];
        // work in coordinates centered at pred box center (better conditioning)
        float dx = qx - px, dy = qy - py;

        float ca, sa; __sincosf(pa, &sa, &ca);
        float cb, sb; __sincosf(qa, &sb, &cb);

        const float tx[4] = {0.5f, -0.5f, -0.5f, 0.5f};
        const float ty[4] = {0.5f, 0.5f, -0.5f, -0.5f};
        float c2x[4], c2y[4];
        float ax[8], ay[8], bx[8], by[8];
#pragma unroll
        for (int k = 0; k < 4; k++) {
            float cx0 = tx[k] * pw, cy0 = ty[k] * ph;
            ax[k] = cx0 * ca - cy0 * sa;          // subject polygon: box1 (CCW)
            ay[k] = cx0 * sa + cy0 * ca;
            float cx1 = tx[k] * qw, cy1 = ty[k] * qh;
            c2x[k] = cx1 * cb - cy1 * sb + dx;    // clip polygon: box2 (CCW)
            c2y[k] = cx1 * sb + cy1 * cb + dy;
        }

        // ---- clip box1 by the 4 half-planes of box2 ----
        float *inx = ax, *iny = ay, *outx = bx, *outy = by;
        int nv = 4;
#pragma unroll
        for (int e = 0; e < 4; e++) {
            int en = (e + 1) & 3;
            float e0x = c2x[e], e0y = c2y[e];
            float edx = c2x[en] - e0x, edy = c2y[en] - e0y;
            int nv2 = 0;
            float s0 = xcross(edx, edy, inx[0] - e0x, iny[0] - e0y);
            float scur = s0;
            for (int k = 0; k < nv; k++) {
                int kn = (k + 1 == nv) ? 0 : k + 1;
                float cx0 = inx[k], cy0 = iny[k];
                float nx0 = inx[kn], ny0 = iny[kn];
                float snext = (kn == 0) ? s0
                            : xcross(edx, edy, nx0 - e0x, ny0 - e0y);
                bool cin = (scur >= 0.f);
                bool nin = (snext >= 0.f);
                if (cin) { outx[nv2] = cx0; outy[nv2] = cy0; nv2++; }
                if (cin != nin) {
                    float t = __fdividef(scur, scur - snext);
                    outx[nv2] = cx0 + t * (nx0 - cx0);
                    outy[nv2] = cy0 + t * (ny0 - cy0);
                    nv2++;
                }
                scur = snext;
            }
            nv = nv2;
            float* tmp;
            tmp = inx; inx = outx; outx = tmp;
            tmp = iny; iny = outy; outy = tmp;
            if (nv < 3) { nv = 0; break; }
        }

        // ---- shoelace (polygon already in cyclic order) ----
        float inter = 0.f;
        if (nv >= 3) {
            float s = 0.f;
            float lx = inx[nv - 1], ly = iny[nv - 1];
            for (int k = 0; k < nv; k++) {
                float cx0 = inx[k], cy0 = iny[k];
                s += lx * cy0 - ly * cx0;
                lx = cx0; ly = cy0;
            }
            inter = 0.5f * fabsf(s);
        }

        float a1 = pw * ph, a2 = qw * qh;
        float iou = __fdividef(inter, a1 + a2 - inter);
        iou = fmaxf(iou, IOU_EPS);
        loss = -__logf(iou) * weight[i];
    }

    // ---- block reduction -> per-block partial (no atomics, no zero pass) ----
    unsigned mask = 0xFFFFFFFFu;
#pragma unroll
    for (int o = 16; o > 0; o >>= 1)
        loss += __shfl_down_sync(mask, loss, o);

    __shared__ float ws[BLOCK / 32];
    int lane = threadIdx.x & 31;
    int wid = threadIdx.x >> 5;
    if (lane == 0) ws[wid] = loss;
    __syncthreads();
    if (wid == 0) {
        float v = (lane < (BLOCK / 32)) ? ws[lane] : 0.f;
#pragma unroll
        for (int o = 4; o > 0; o >>= 1)
            v += __shfl_down_sync(mask, v, o);
        if (lane == 0) g_partial[blockIdx.x] = v;
    }
}

__global__ void __launch_bounds__(256)
rl_final(float* __restrict__ out, int nb, float inv_n) {
    double s = 0.0;
    for (int j = threadIdx.x; j < nb; j += 256)
        s += (double)g_partial[j];

    unsigned mask = 0xFFFFFFFFu;
#pragma unroll
    for (int o = 16; o > 0; o >>= 1)
        s += __shfl_down_sync(mask, s, o);

    __shared__ double ds[8];
    int lane = threadIdx.x & 31;
    int wid = threadIdx.x >> 5;
    if (lane == 0) ds[wid] = s;
    __syncthreads();
    if (wid == 0) {
        double v = (lane < 8) ? ds[lane] : 0.0;
#pragma unroll
        for (int o = 4; o > 0; o >>= 1)
            v += __shfl_down_sync(mask, v, o);
        if (lane == 0) out[0] = (float)(v * (double)inv_n);
    }
}

extern "C" void kernel_launch(void* const* d_in, const int* in_sizes, int n_in,
                              void* d_out, int out_size) {
    const float* pred   = (const float*)d_in[0];
    const float* target = (const float*)d_in[1];
    const float* weight = (const float*)d_in[2];
    float* out = (float*)d_out;
    int n = in_sizes[2];

    int grid = (n + BLOCK - 1) / BLOCK;
    if (grid > MAXB) grid = MAXB;  // n is 1e6 -> 3907; guard only
    rl_main<<<grid, BLOCK>>>(pred, target, weight, n);
    rl_final<<<1, 256>>>(out, grid, 1.0f / (float)n);
}